// round 2
// baseline (speedup 1.0000x reference)
#include <cuda_runtime.h>
#include <math.h>

// Problem constants
#define B_SZ    2
#define T_SEQ   2048
#define M_ROWS  8192        // B*T
#define D_MODEL 4096
#define D_KV    1024
#define HD      128
#define NH      32
#define NKV     8

// Scratch: __device__ globals (allocation-free rule). Referenced DIRECTLY by
// kernels via selector — no cudaGetSymbolAddress on the host.
__device__ __align__(256) float g_q[(size_t)M_ROWS * D_MODEL];   // 128 MB
__device__ __align__(256) float g_k[(size_t)M_ROWS * D_KV];      // 32 MB
__device__ __align__(256) float g_v[(size_t)M_ROWS * D_KV];      // 32 MB
__device__ __align__(256) float g_ctx[(size_t)M_ROWS * D_MODEL]; // 128 MB

__device__ __forceinline__ float* scratch_buf(int sel) {
    switch (sel) {
        case 0:  return g_q;
        case 1:  return g_k;
        case 2:  return g_v;
        default: return g_ctx;
    }
}

// ---------------------------------------------------------------------------
// NT GEMM: C[m,n] = sum_k A[m,k] * W[n,k]
// 128x128 tile, BK=16, 256 threads, 8x8 per thread.
// All accesses to harness-owned memory are scalar + bounds-guarded.
// ---------------------------------------------------------------------------
__global__ __launch_bounds__(256, 2) void gemm_nt_kernel(
    const float* __restrict__ Aparam, int a_sel, long long a_lim,
    const float* __restrict__ W, long long w_lim,
    float* __restrict__ Cparam, int c_sel, long long c_lim,
    int M, int N, int K) {
    const float* A = (a_sel < 0) ? Aparam : scratch_buf(a_sel);
    float* C = (c_sel < 0) ? Cparam : scratch_buf(c_sel);

    __shared__ __align__(16) float As[16][128];
    __shared__ __align__(16) float Ws[16][128];

    const int tid = threadIdx.x;
    const int bm = blockIdx.y << 7;
    const int bn = blockIdx.x << 7;
    const int ty = tid >> 4;
    const int tx = tid & 15;

    float acc[8][8];
#pragma unroll
    for (int i = 0; i < 8; i++)
#pragma unroll
        for (int j = 0; j < 8; j++) acc[i][j] = 0.f;

    for (int k0 = 0; k0 < K; k0 += 16) {
        // Load 128x16 tiles of A and W (scalar, coalesced along k).
#pragma unroll
        for (int it = 0; it < 8; it++) {
            int idx = it * 256 + tid;
            int row = idx >> 4;       // 0..127
            int kc = idx & 15;        // 0..15
            size_t aoff = (size_t)(bm + row) * K + k0 + kc;
            size_t woff = (size_t)(bn + row) * K + k0 + kc;
            float av = 0.f, wv = 0.f;
            if (a_sel >= 0 || (long long)aoff < a_lim) av = A[aoff];
            if ((long long)woff < w_lim) wv = W[woff];
            As[kc][row] = av;
            Ws[kc][row] = wv;
        }
        __syncthreads();
#pragma unroll
        for (int kk = 0; kk < 16; kk++) {
            float4 a0 = *(const float4*)&As[kk][ty << 3];
            float4 a1 = *(const float4*)&As[kk][(ty << 3) + 4];
            float4 b0 = *(const float4*)&Ws[kk][tx << 3];
            float4 b1 = *(const float4*)&Ws[kk][(tx << 3) + 4];
            float a[8] = {a0.x, a0.y, a0.z, a0.w, a1.x, a1.y, a1.z, a1.w};
            float b[8] = {b0.x, b0.y, b0.z, b0.w, b1.x, b1.y, b1.z, b1.w};
#pragma unroll
            for (int i = 0; i < 8; i++)
#pragma unroll
                for (int j = 0; j < 8; j++)
                    acc[i][j] = fmaf(a[i], b[j], acc[i][j]);
        }
        __syncthreads();
    }

#pragma unroll
    for (int i = 0; i < 8; i++) {
        size_t rowoff = (size_t)(bm + (ty << 3) + i) * N + bn + (tx << 3);
#pragma unroll
        for (int j = 0; j < 8; j++) {
            size_t off = rowoff + j;
            if (c_sel >= 0 || (long long)off < c_lim) C[off] = acc[i][j];
        }
    }
}

// ---------------------------------------------------------------------------
// RoPE in-place on scratch [M_ROWS, nheads*128]; pair (2d, 2d+1) per head.
// ---------------------------------------------------------------------------
__global__ void rope_kernel(int sel,
                            const float* __restrict__ cosv, long long cos_lim,
                            const float* __restrict__ sinv, long long sin_lim,
                            int nheads) {
    float* t = scratch_buf(sel);
    int idx = blockIdx.x * blockDim.x + threadIdx.x;
    int d = idx & 63;
    int head = (idx >> 6) % nheads;
    int row = idx / (nheads * 64);
    if (row >= M_ROWS) return;
    int tpos = row & (T_SEQ - 1);  // start_pos = 0
    long long coff = (long long)tpos * 64 + d;
    float c = (coff < cos_lim) ? cosv[coff] : 0.f;
    float s = (coff < sin_lim) ? sinv[coff] : 0.f;
    size_t base = (size_t)row * (nheads * HD) + head * HD + 2 * d;
    float re = t[base];
    float im = t[base + 1];
    t[base]     = re * c - im * s;
    t[base + 1] = re * s + im * c;
}

// ---------------------------------------------------------------------------
// Flash attention (non-causal, full 2048 keys), fp32, online softmax.
// Operates entirely on aligned scratch; dynamic smem base is 16B-aligned.
// ---------------------------------------------------------------------------
#define QROW 132
#define PROW 68

__global__ __launch_bounds__(256) void flash_kernel() {
    const float* __restrict__ Q  = g_q;
    const float* __restrict__ Kg = g_k;
    const float* __restrict__ Vg = g_v;
    float* __restrict__ Ctx = g_ctx;

    extern __shared__ float sm[];
    float* Qs  = sm;                    // 64 * QROW
    float* KVs = sm + 64 * QROW;        // 64 * QROW
    float* Ps  = KVs + 64 * QROW;       // 64 * PROW

    const int tid = threadIdx.x;
    const int ty = tid >> 4;
    const int tx = tid & 15;
    const int bh = blockIdx.y;          // 0..63
    const int b = bh >> 5;
    const int h = bh & 31;
    const int kvh = h >> 2;
    const int t0 = blockIdx.x << 6;

    const float* qb = Q  + (size_t)(b * T_SEQ + t0) * D_MODEL + h * HD;
    const float* kb = Kg + (size_t)(b * T_SEQ) * D_KV + kvh * HD;
    const float* vb = Vg + (size_t)(b * T_SEQ) * D_KV + kvh * HD;
    const float scale = 0.08838834764831845f;  // 1/sqrt(128)

    for (int i = tid; i < 64 * 32; i += 256) {
        int r = i >> 5;
        int c = (i & 31) << 2;
        float4 v = *(const float4*)(qb + (size_t)r * D_MODEL + c);
        float* dst = Qs + r * QROW + c;
        dst[0] = v.x * scale; dst[1] = v.y * scale;
        dst[2] = v.z * scale; dst[3] = v.w * scale;
    }

    float m_i[4], l_i[4], o[4][8];
#pragma unroll
    for (int i = 0; i < 4; i++) {
        m_i[i] = -1e30f;
        l_i[i] = 0.f;
#pragma unroll
        for (int j = 0; j < 8; j++) o[i][j] = 0.f;
    }

    for (int s0 = 0; s0 < T_SEQ; s0 += 64) {
        for (int i = tid; i < 64 * 32; i += 256) {
            int r = i >> 5;
            int c = (i & 31) << 2;
            float4 v = *(const float4*)(kb + (size_t)(s0 + r) * D_KV + c);
            float* dst = KVs + r * QROW + c;
            dst[0] = v.x; dst[1] = v.y; dst[2] = v.z; dst[3] = v.w;
        }
        __syncthreads();

        float sacc[4][4];
#pragma unroll
        for (int i = 0; i < 4; i++)
#pragma unroll
            for (int j = 0; j < 4; j++) sacc[i][j] = 0.f;

        for (int kk = 0; kk < 128; kk += 4) {
            float4 a[4], bb[4];
#pragma unroll
            for (int i = 0; i < 4; i++)
                a[i] = *(const float4*)&Qs[(ty * 4 + i) * QROW + kk];
#pragma unroll
            for (int j = 0; j < 4; j++)
                bb[j] = *(const float4*)&KVs[(tx * 4 + j) * QROW + kk];
#pragma unroll
            for (int i = 0; i < 4; i++)
#pragma unroll
                for (int j = 0; j < 4; j++) {
                    sacc[i][j] = fmaf(a[i].x, bb[j].x, sacc[i][j]);
                    sacc[i][j] = fmaf(a[i].y, bb[j].y, sacc[i][j]);
                    sacc[i][j] = fmaf(a[i].z, bb[j].z, sacc[i][j]);
                    sacc[i][j] = fmaf(a[i].w, bb[j].w, sacc[i][j]);
                }
        }

#pragma unroll
        for (int i = 0; i < 4; i++) {
            float mx = fmaxf(fmaxf(sacc[i][0], sacc[i][1]),
                             fmaxf(sacc[i][2], sacc[i][3]));
#pragma unroll
            for (int off = 1; off < 16; off <<= 1)
                mx = fmaxf(mx, __shfl_xor_sync(0xffffffffu, mx, off));
            float mnew = fmaxf(m_i[i], mx);
            float corr = expf(m_i[i] - mnew);
            m_i[i] = mnew;
            float p0 = expf(sacc[i][0] - mnew);
            float p1 = expf(sacc[i][1] - mnew);
            float p2 = expf(sacc[i][2] - mnew);
            float p3 = expf(sacc[i][3] - mnew);
            float rsum = p0 + p1 + p2 + p3;
#pragma unroll
            for (int off = 1; off < 16; off <<= 1)
                rsum += __shfl_xor_sync(0xffffffffu, rsum, off);
            l_i[i] = l_i[i] * corr + rsum;
#pragma unroll
            for (int j = 0; j < 8; j++) o[i][j] *= corr;
            float* pr = Ps + (ty * 4 + i) * PROW + tx * 4;
            pr[0] = p0; pr[1] = p1; pr[2] = p2; pr[3] = p3;
        }
        __syncthreads();

        for (int i = tid; i < 64 * 32; i += 256) {
            int r = i >> 5;
            int c = (i & 31) << 2;
            float4 v = *(const float4*)(vb + (size_t)(s0 + r) * D_KV + c);
            float* dst = KVs + r * QROW + c;
            dst[0] = v.x; dst[1] = v.y; dst[2] = v.z; dst[3] = v.w;
        }
        __syncthreads();

        for (int ss = 0; ss < 64; ss++) {
            float4 v0 = *(const float4*)&KVs[ss * QROW + tx * 8];
            float4 v1 = *(const float4*)&KVs[ss * QROW + tx * 8 + 4];
#pragma unroll
            for (int i = 0; i < 4; i++) {
                float p = Ps[(ty * 4 + i) * PROW + ss];
                o[i][0] = fmaf(p, v0.x, o[i][0]);
                o[i][1] = fmaf(p, v0.y, o[i][1]);
                o[i][2] = fmaf(p, v0.z, o[i][2]);
                o[i][3] = fmaf(p, v0.w, o[i][3]);
                o[i][4] = fmaf(p, v1.x, o[i][4]);
                o[i][5] = fmaf(p, v1.y, o[i][5]);
                o[i][6] = fmaf(p, v1.z, o[i][6]);
                o[i][7] = fmaf(p, v1.w, o[i][7]);
            }
        }
        __syncthreads();
    }

#pragma unroll
    for (int i = 0; i < 4; i++) {
        float inv = 1.f / l_i[i];
        size_t row = (size_t)(b * T_SEQ + t0 + ty * 4 + i);
        float* dst = Ctx + row * D_MODEL + h * HD + tx * 8;
#pragma unroll
        for (int j = 0; j < 8; j++) dst[j] = o[i][j] * inv;
    }
}

// ---------------------------------------------------------------------------
// Launch
// ---------------------------------------------------------------------------
extern "C" void kernel_launch(void* const* d_in, const int* in_sizes, int n_in,
                              void* d_out, int out_size) {
    const float* x    = (const float*)d_in[0];
    const float* wq   = (const float*)d_in[1];
    const float* wk   = (const float*)d_in[2];
    const float* wv   = (const float*)d_in[3];
    const float* wo   = (const float*)d_in[4];
    const float* cosv = (const float*)d_in[7];
    const float* sinv = (const float*)d_in[8];
    float* out = (float*)d_out;

    long long xl  = in_sizes[0];
    long long wql = in_sizes[1];
    long long wkl = in_sizes[2];
    long long wvl = in_sizes[3];
    long long wol = in_sizes[4];
    long long cl  = in_sizes[7];
    long long sl  = in_sizes[8];
    long long ol  = out_size;

    const int FLASH_SMEM = (64 * QROW * 2 + 64 * PROW) * 4;  // 84992 bytes
    cudaFuncSetAttribute(flash_kernel,
                         cudaFuncAttributeMaxDynamicSharedMemorySize, FLASH_SMEM);

    // Projections: q = x wq^T, k = x wk^T, v = x wv^T
    gemm_nt_kernel<<<dim3(32, 64), 256>>>(x, -1, xl, wq, wql,
                                          nullptr, 0, 0, M_ROWS, D_MODEL, D_MODEL);
    gemm_nt_kernel<<<dim3(8, 64), 256>>>(x, -1, xl, wk, wkl,
                                         nullptr, 1, 0, M_ROWS, D_KV, D_MODEL);
    gemm_nt_kernel<<<dim3(8, 64), 256>>>(x, -1, xl, wv, wvl,
                                         nullptr, 2, 0, M_ROWS, D_KV, D_MODEL);

    // RoPE on q (32 heads) and k (8 heads)
    rope_kernel<<<(M_ROWS * NH * 64) / 256, 256>>>(0, cosv, cl, sinv, sl, NH);
    rope_kernel<<<(M_ROWS * NKV * 64) / 256, 256>>>(1, cosv, cl, sinv, sl, NKV);

    // Attention
    flash_kernel<<<dim3(T_SEQ / 64, B_SZ * NH), 256, FLASH_SMEM>>>();

    // Output projection: out = ctx wo^T
    gemm_nt_kernel<<<dim3(32, 64), 256>>>(nullptr, 3, 0, wo, wol,
                                          out, -1, ol, M_ROWS, D_MODEL, D_MODEL);
}

// round 10
// speedup vs baseline: 1.2134x; 1.2134x over previous
#include <cuda_runtime.h>
#include <math.h>
#include <stdint.h>

// Problem constants
#define B_SZ    2
#define T_SEQ   2048
#define M_ROWS  8192
#define D_MODEL 4096
#define D_KV    1024
#define HD      128
#define NH      32
#define NKV     8

// ---------------------------------------------------------------------------
// Scratch: round-2 (passing) footprint — 320 MB, fp32 only.
// ---------------------------------------------------------------------------
__device__ __align__(256) float g_q[(size_t)M_ROWS * D_MODEL];
__device__ __align__(256) float g_k[(size_t)M_ROWS * D_KV];
__device__ __align__(256) float g_v[(size_t)M_ROWS * D_KV];
__device__ __align__(256) float g_ctx[(size_t)M_ROWS * D_MODEL];

__device__ __forceinline__ float* f32_buf(int sel) {
    switch (sel) {
        case 0:  return g_q;
        case 1:  return g_k;
        case 2:  return g_v;
        default: return g_ctx;
    }
}

// ---------------------------------------------------------------------------
// Packed f32x2 helpers (Blackwell FMA pipe; register-only; NOT tensor path)
// ---------------------------------------------------------------------------
typedef unsigned long long u64t;

__device__ __forceinline__ void fma2(u64t& d, u64t a, u64t b) {
    asm("fma.rn.f32x2 %0, %1, %2, %0;" : "+l"(d) : "l"(a), "l"(b));
}
__device__ __forceinline__ u64t mul2(u64t a, u64t b) {
    u64t d;
    asm("mul.rn.f32x2 %0, %1, %2;" : "=l"(d) : "l"(a), "l"(b));
    return d;
}
__device__ __forceinline__ u64t dup2(float x) {
    u64t d;
    asm("mov.b64 %0, {%1, %1};" : "=l"(d) : "f"(x));
    return d;
}
__device__ __forceinline__ float2 unpack2(u64t v) {
    float2 f;
    asm("mov.b64 {%0, %1}, %2;" : "=f"(f.x), "=f"(f.y) : "l"(v));
    return f;
}

// ---------------------------------------------------------------------------
// NT GEMM with packed fma.rn.f32x2: C[m,n] = sum_k A[m,k]*W[n,k].
// Round-2 structure: 128x128 tile, BK=16, 256 threads, 8x8/thread,
// load->sync->compute->sync, all harness access scalar + guarded.
// Smem: Adup[kk][2m]={A[m],A[m]} (dup pairs -> free broadcast),
//       Ws[kk][n] plain (natural pairs along n).
// ---------------------------------------------------------------------------
#define ADROW 260     // floats per Adup row (pad: 16B-aligned rows, spread banks)
#define WSROW 132     // floats per Ws row

__global__ __launch_bounds__(256, 2) void gemm_nt_kernel(
    const float* __restrict__ Aparam, int a_sel, long long a_lim,
    const float* __restrict__ W, long long w_lim,
    float* __restrict__ Cparam, int c_sel, long long c_lim,
    int M, int N, int K) {
    const float* A = (a_sel < 0) ? Aparam : f32_buf(a_sel);
    float* C = (c_sel < 0) ? Cparam : f32_buf(c_sel);

    __shared__ __align__(16) float Adup[16][ADROW];  // 16640 B
    __shared__ __align__(16) float Ws[16][WSROW];    //  8448 B

    const int tid = threadIdx.x;
    const int bm = blockIdx.y << 7;
    const int bn = blockIdx.x << 7;
    const int ty = tid >> 4;
    const int tx = tid & 15;

    u64t acc2[8][4];
#pragma unroll
    for (int i = 0; i < 8; i++)
#pragma unroll
        for (int j = 0; j < 4; j++) acc2[i][j] = 0ull;

    for (int k0 = 0; k0 < K; k0 += 16) {
        // Load 128x16 tiles (round-2 mapping: coalesced LDG, guarded)
#pragma unroll
        for (int it = 0; it < 8; it++) {
            int idx = it * 256 + tid;
            int row = idx >> 4;       // 0..127
            int kc = idx & 15;        // 0..15
            size_t aoff = (size_t)(bm + row) * K + k0 + kc;
            size_t woff = (size_t)(bn + row) * K + k0 + kc;
            float av = 0.f, wv = 0.f;
            if (a_sel >= 0 || (long long)aoff < a_lim) av = A[aoff];
            if ((long long)woff < w_lim) wv = W[woff];
            *(float2*)&Adup[kc][2 * row] = make_float2(av, av);
            Ws[kc][row] = wv;
        }
        __syncthreads();
#pragma unroll
        for (int kk = 0; kk < 16; kk++) {
            // a2[i] = {a_i, a_i} for thread rows m0 = ty*8 .. +7
            ulonglong2 a01 = *(const ulonglong2*)&Adup[kk][ty * 16];
            ulonglong2 a23 = *(const ulonglong2*)&Adup[kk][ty * 16 + 4];
            ulonglong2 a45 = *(const ulonglong2*)&Adup[kk][ty * 16 + 8];
            ulonglong2 a67 = *(const ulonglong2*)&Adup[kk][ty * 16 + 12];
            u64t a2[8] = {a01.x, a01.y, a23.x, a23.y,
                          a45.x, a45.y, a67.x, a67.y};
            // b2[j2] = {b_2j2, b_2j2+1} for thread cols n0 = tx*8 .. +7
            ulonglong2 b01 = *(const ulonglong2*)&Ws[kk][tx * 8];
            ulonglong2 b23 = *(const ulonglong2*)&Ws[kk][tx * 8 + 4];
            u64t b2[4] = {b01.x, b01.y, b23.x, b23.y};
#pragma unroll
            for (int i = 0; i < 8; i++)
#pragma unroll
                for (int j = 0; j < 4; j++)
                    fma2(acc2[i][j], a2[i], b2[j]);
        }
        __syncthreads();
    }

    // Epilogue: scalar stores, guarded (round-2 style)
#pragma unroll
    for (int i = 0; i < 8; i++) {
        size_t rowoff = (size_t)(bm + (ty << 3) + i) * N + bn + (tx << 3);
#pragma unroll
        for (int j = 0; j < 4; j++) {
            float2 v = unpack2(acc2[i][j]);
            size_t off = rowoff + 2 * j;
            if (c_sel >= 0 || (long long)off < c_lim) C[off] = v.x;
            if (c_sel >= 0 || (long long)(off + 1) < c_lim) C[off + 1] = v.y;
        }
    }
}

// ---------------------------------------------------------------------------
// RoPE (round-2 verbatim)
// ---------------------------------------------------------------------------
__global__ void rope_kernel(int sel,
                            const float* __restrict__ cosv, long long cos_lim,
                            const float* __restrict__ sinv, long long sin_lim,
                            int nheads) {
    float* t = f32_buf(sel);
    int idx = blockIdx.x * blockDim.x + threadIdx.x;
    int d = idx & 63;
    int head = (idx >> 6) % nheads;
    int row = idx / (nheads * 64);
    if (row >= M_ROWS) return;
    int tpos = row & (T_SEQ - 1);
    long long coff = (long long)tpos * 64 + d;
    float c = (coff < cos_lim) ? cosv[coff] : 0.f;
    float s = (coff < sin_lim) ? sinv[coff] : 0.f;
    size_t base = (size_t)row * (nheads * HD) + head * HD + 2 * d;
    float re = t[base];
    float im = t[base + 1];
    t[base]     = re * c - im * s;
    t[base + 1] = re * s + im * c;
}

// ---------------------------------------------------------------------------
// Flash attention: round-2 structure, inner loops packed with f32x2.
// QK^T: even/odd-k partials in packed lanes, reduced before softmax.
// PV:   dup-packed p times natural v pairs.
// ---------------------------------------------------------------------------
#define QROW 132
#define PROW 68

__global__ __launch_bounds__(256) void flash_kernel() {
    const float* __restrict__ Q  = g_q;
    const float* __restrict__ Kg = g_k;
    const float* __restrict__ Vg = g_v;
    float* __restrict__ Ctx = g_ctx;

    extern __shared__ float sm[];
    float* Qs  = sm;
    float* KVs = sm + 64 * QROW;
    float* Ps  = KVs + 64 * QROW;

    const int tid = threadIdx.x;
    const int ty = tid >> 4;
    const int tx = tid & 15;
    const int bh = blockIdx.y;
    const int b = bh >> 5;
    const int h = bh & 31;
    const int kvh = h >> 2;
    const int t0 = blockIdx.x << 6;

    const float* qb = Q  + (size_t)(b * T_SEQ + t0) * D_MODEL + h * HD;
    const float* kb = Kg + (size_t)(b * T_SEQ) * D_KV + kvh * HD;
    const float* vb = Vg + (size_t)(b * T_SEQ) * D_KV + kvh * HD;
    const float scale = 0.08838834764831845f;

    for (int i = tid; i < 64 * 32; i += 256) {
        int r = i >> 5;
        int c = (i & 31) << 2;
        float4 v = *(const float4*)(qb + (size_t)r * D_MODEL + c);
        float* dst = Qs + r * QROW + c;
        dst[0] = v.x * scale; dst[1] = v.y * scale;
        dst[2] = v.z * scale; dst[3] = v.w * scale;
    }

    float m_i[4], l_i[4];
    u64t o2[4][4];   // packed output cols: o2[i][j2] = {o[2j2], o[2j2+1]}
#pragma unroll
    for (int i = 0; i < 4; i++) {
        m_i[i] = -1e30f;
        l_i[i] = 0.f;
#pragma unroll
        for (int j = 0; j < 4; j++) o2[i][j] = 0ull;
    }

    for (int s0 = 0; s0 < T_SEQ; s0 += 64) {
        for (int i = tid; i < 64 * 32; i += 256) {
            int r = i >> 5;
            int c = (i & 31) << 2;
            float4 v = *(const float4*)(kb + (size_t)(s0 + r) * D_KV + c);
            float* dst = KVs + r * QROW + c;
            dst[0] = v.x; dst[1] = v.y; dst[2] = v.z; dst[3] = v.w;
        }
        __syncthreads();

        // S = Q K^T, packed partials (lo = even-k, hi = odd-k)
        u64t sacc2[4][4];
#pragma unroll
        for (int i = 0; i < 4; i++)
#pragma unroll
            for (int j = 0; j < 4; j++) sacc2[i][j] = 0ull;

        for (int kk = 0; kk < 128; kk += 4) {
            ulonglong2 a2[4], b2[4];
#pragma unroll
            for (int i = 0; i < 4; i++)
                a2[i] = *(const ulonglong2*)&Qs[(ty * 4 + i) * QROW + kk];
#pragma unroll
            for (int j = 0; j < 4; j++)
                b2[j] = *(const ulonglong2*)&KVs[(tx * 4 + j) * QROW + kk];
#pragma unroll
            for (int i = 0; i < 4; i++)
#pragma unroll
                for (int j = 0; j < 4; j++) {
                    fma2(sacc2[i][j], a2[i].x, b2[j].x);
                    fma2(sacc2[i][j], a2[i].y, b2[j].y);
                }
        }

        // Online softmax (reduce packed lanes first)
#pragma unroll
        for (int i = 0; i < 4; i++) {
            float sc[4];
#pragma unroll
            for (int j = 0; j < 4; j++) {
                float2 p = unpack2(sacc2[i][j]);
                sc[j] = p.x + p.y;
            }
            float mx = fmaxf(fmaxf(sc[0], sc[1]), fmaxf(sc[2], sc[3]));
#pragma unroll
            for (int off = 1; off < 16; off <<= 1)
                mx = fmaxf(mx, __shfl_xor_sync(0xffffffffu, mx, off));
            float mnew = fmaxf(m_i[i], mx);
            float corr = __expf(m_i[i] - mnew);
            m_i[i] = mnew;
            float p0 = __expf(sc[0] - mnew);
            float p1 = __expf(sc[1] - mnew);
            float p2 = __expf(sc[2] - mnew);
            float p3 = __expf(sc[3] - mnew);
            float rsum = p0 + p1 + p2 + p3;
#pragma unroll
            for (int off = 1; off < 16; off <<= 1)
                rsum += __shfl_xor_sync(0xffffffffu, rsum, off);
            l_i[i] = l_i[i] * corr + rsum;
            u64t c2 = dup2(corr);
#pragma unroll
            for (int j = 0; j < 4; j++) o2[i][j] = mul2(o2[i][j], c2);
            float* pr = Ps + (ty * 4 + i) * PROW + tx * 4;
            pr[0] = p0; pr[1] = p1; pr[2] = p2; pr[3] = p3;
        }
        __syncthreads();

        for (int i = tid; i < 64 * 32; i += 256) {
            int r = i >> 5;
            int c = (i & 31) << 2;
            float4 v = *(const float4*)(vb + (size_t)(s0 + r) * D_KV + c);
            float* dst = KVs + r * QROW + c;
            dst[0] = v.x; dst[1] = v.y; dst[2] = v.z; dst[3] = v.w;
        }
        __syncthreads();

        // O += P V, packed
        for (int ss = 0; ss < 64; ss++) {
            ulonglong2 v01 = *(const ulonglong2*)&KVs[ss * QROW + tx * 8];
            ulonglong2 v23 = *(const ulonglong2*)&KVs[ss * QROW + tx * 8 + 4];
#pragma unroll
            for (int i = 0; i < 4; i++) {
                u64t p2v = dup2(Ps[(ty * 4 + i) * PROW + ss]);
                fma2(o2[i][0], p2v, v01.x);
                fma2(o2[i][1], p2v, v01.y);
                fma2(o2[i][2], p2v, v23.x);
                fma2(o2[i][3], p2v, v23.y);
            }
        }
        __syncthreads();
    }

    // Epilogue: normalize, unpack, write ctx
#pragma unroll
    for (int i = 0; i < 4; i++) {
        float inv = 1.f / l_i[i];
        size_t row = (size_t)(b * T_SEQ + t0 + ty * 4 + i);
        float* dst = Ctx + row * D_MODEL + h * HD + tx * 8;
#pragma unroll
        for (int j = 0; j < 4; j++) {
            float2 v = unpack2(o2[i][j]);
            dst[2 * j] = v.x * inv;
            dst[2 * j + 1] = v.y * inv;
        }
    }
}

// ---------------------------------------------------------------------------
// Launch (round-2 grids)
// ---------------------------------------------------------------------------
extern "C" void kernel_launch(void* const* d_in, const int* in_sizes, int n_in,
                              void* d_out, int out_size) {
    const float* x    = (const float*)d_in[0];
    const float* wq   = (const float*)d_in[1];
    const float* wk   = (const float*)d_in[2];
    const float* wv   = (const float*)d_in[3];
    const float* wo   = (const float*)d_in[4];
    const float* cosv = (const float*)d_in[7];
    const float* sinv = (const float*)d_in[8];
    float* out = (float*)d_out;

    long long xl  = in_sizes[0];
    long long wql = in_sizes[1];
    long long wkl = in_sizes[2];
    long long wvl = in_sizes[3];
    long long wol = in_sizes[4];
    long long cl  = in_sizes[7];
    long long sl  = in_sizes[8];
    long long ol  = out_size;

    const int FLASH_SMEM = (64 * QROW * 2 + 64 * PROW) * 4;  // 84992 bytes
    cudaFuncSetAttribute(flash_kernel,
                         cudaFuncAttributeMaxDynamicSharedMemorySize, FLASH_SMEM);

    // Projections: q = x wq^T, k = x wk^T, v = x wv^T
    gemm_nt_kernel<<<dim3(32, 64), 256>>>(x, -1, xl, wq, wql,
                                          nullptr, 0, 0, M_ROWS, D_MODEL, D_MODEL);
    gemm_nt_kernel<<<dim3(8, 64), 256>>>(x, -1, xl, wk, wkl,
                                         nullptr, 1, 0, M_ROWS, D_KV, D_MODEL);
    gemm_nt_kernel<<<dim3(8, 64), 256>>>(x, -1, xl, wv, wvl,
                                         nullptr, 2, 0, M_ROWS, D_KV, D_MODEL);

    // RoPE on q (32 heads) and k (8 heads)
    rope_kernel<<<(M_ROWS * NH * 64) / 256, 256>>>(0, cosv, cl, sinv, sl, NH);
    rope_kernel<<<(M_ROWS * NKV * 64) / 256, 256>>>(1, cosv, cl, sinv, sl, NKV);

    // Attention
    flash_kernel<<<dim3(T_SEQ / 64, B_SZ * NH), 256, FLASH_SMEM>>>();

    // Output projection: out = ctx wo^T
    gemm_nt_kernel<<<dim3(32, 64), 256>>>(nullptr, 3, 0, wo, wol,
                                          out, -1, ol, M_ROWS, D_MODEL, D_MODEL);
}

// round 11
// speedup vs baseline: 1.2147x; 1.0010x over previous
#include <cuda_runtime.h>
#include <math.h>
#include <stdint.h>

// Problem constants
#define B_SZ    2
#define T_SEQ   2048
#define M_ROWS  8192
#define D_MODEL 4096
#define D_KV    1024
#define HD      128
#define NH      32
#define NKV     8

// ---------------------------------------------------------------------------
// Scratch: proven-safe footprint — 320 MB, fp32 only.
// ---------------------------------------------------------------------------
__device__ __align__(256) float g_q[(size_t)M_ROWS * D_MODEL];
__device__ __align__(256) float g_k[(size_t)M_ROWS * D_KV];
__device__ __align__(256) float g_v[(size_t)M_ROWS * D_KV];
__device__ __align__(256) float g_ctx[(size_t)M_ROWS * D_MODEL];

__device__ __forceinline__ float* f32_buf(int sel) {
    switch (sel) {
        case 0:  return g_q;
        case 1:  return g_k;
        case 2:  return g_v;
        default: return g_ctx;
    }
}

// ---------------------------------------------------------------------------
// Packed f32x2 helpers (FMA pipe, register-only)
// ---------------------------------------------------------------------------
typedef unsigned long long u64t;

__device__ __forceinline__ void fma2(u64t& d, u64t a, u64t b) {
    asm("fma.rn.f32x2 %0, %1, %2, %0;" : "+l"(d) : "l"(a), "l"(b));
}
__device__ __forceinline__ u64t mul2(u64t a, u64t b) {
    u64t d;
    asm("mul.rn.f32x2 %0, %1, %2;" : "=l"(d) : "l"(a), "l"(b));
    return d;
}
__device__ __forceinline__ u64t dup2(float x) {
    u64t d;
    asm("mov.b64 %0, {%1, %1};" : "=l"(d) : "f"(x));
    return d;
}
__device__ __forceinline__ float2 unpack2(u64t v) {
    float2 f;
    asm("mov.b64 {%0, %1}, %2;" : "=f"(f.x), "=f"(f.y) : "l"(v));
    return f;
}

// ---------------------------------------------------------------------------
// NT GEMM v2: C[m,n] = sum_k A[m,k]*W[n,k], fma.rn.f32x2 pipe.
// CTA tile 128(m) x 256(n), 256 threads, thread tile 8x16 (64 fma2/kk).
// Single-buffer smem + REGISTER PREFETCH of next chunk during compute.
// A stored plain (dup to packed via ALU mov); W stored in 36-float-stride
// groups of 16 -> conflict-free LDS.128 (banks 4*tx mod 32 distinct, 16B
// aligned). All harness-memory access scalar + guarded.
// ---------------------------------------------------------------------------
#define BK2      16
#define AS_ROW   132                    // floats per kk-row of As
#define WS_GRP   36                     // float stride per 16-col group
#define WS_ROW   (16 * WS_GRP)          // 576 floats per kk-row of Ws
#define AS_ELEMS (BK2 * AS_ROW)         // 2112
#define WS_ELEMS (BK2 * WS_ROW)         // 9216

__global__ __launch_bounds__(256, 1) void gemm_nt_kernel(
    const float* __restrict__ Aparam, int a_sel, long long a_lim,
    const float* __restrict__ W, long long w_lim,
    float* __restrict__ Cparam, int c_sel, long long c_lim,
    int M, int N, int K) {
    const float* A = (a_sel < 0) ? Aparam : f32_buf(a_sel);
    float* C = (c_sel < 0) ? Cparam : f32_buf(c_sel);

    __shared__ __align__(16) float As[AS_ELEMS];   // 8448 B
    __shared__ __align__(16) float Ws[WS_ELEMS];   // 36864 B

    const int tid = threadIdx.x;
    const int ty = tid >> 4;        // 0..15 -> rows ty*8..+7
    const int tx = tid & 15;        // 0..15 -> cols tx*16..+15
    const int bm = blockIdx.y << 7;
    const int bn = blockIdx.x << 8;

    u64t acc2[8][8];
#pragma unroll
    for (int i = 0; i < 8; i++)
#pragma unroll
        for (int j = 0; j < 8; j++) acc2[i][j] = 0ull;

    float pa[8], pw[16];

    // --- load chunk 0 into registers (scalar, guarded) ---
#pragma unroll
    for (int it = 0; it < 8; it++) {
        int idx = it * 256 + tid;
        int row = idx >> 4, kc = idx & 15;
        size_t aoff = (size_t)(bm + row) * K + kc;
        pa[it] = (a_sel >= 0 || (long long)aoff < a_lim) ? A[aoff] : 0.f;
    }
#pragma unroll
    for (int it = 0; it < 16; it++) {
        int idx = it * 256 + tid;
        int n = idx >> 4, kc = idx & 15;
        size_t woff = (size_t)(bn + n) * K + kc;
        pw[it] = ((long long)woff < w_lim) ? W[woff] : 0.f;
    }
    // store chunk 0
#pragma unroll
    for (int it = 0; it < 8; it++) {
        int idx = it * 256 + tid;
        int row = idx >> 4, kc = idx & 15;
        As[kc * AS_ROW + row] = pa[it];
    }
#pragma unroll
    for (int it = 0; it < 16; it++) {
        int idx = it * 256 + tid;
        int n = idx >> 4, kc = idx & 15;
        Ws[kc * WS_ROW + (n >> 4) * WS_GRP + (n & 15)] = pw[it];
    }
    __syncthreads();

    const int nchunks = K / BK2;     // 256 for K=4096
    for (int c = 0; c < nchunks; c++) {
        // Prefetch next chunk into registers (overlaps with compute below)
        if (c + 1 < nchunks) {
            const int k0 = (c + 1) * BK2;
#pragma unroll
            for (int it = 0; it < 8; it++) {
                int idx = it * 256 + tid;
                int row = idx >> 4, kc = idx & 15;
                size_t aoff = (size_t)(bm + row) * K + k0 + kc;
                pa[it] = (a_sel >= 0 || (long long)aoff < a_lim) ? A[aoff] : 0.f;
            }
#pragma unroll
            for (int it = 0; it < 16; it++) {
                int idx = it * 256 + tid;
                int n = idx >> 4, kc = idx & 15;
                size_t woff = (size_t)(bn + n) * K + k0 + kc;
                pw[it] = ((long long)woff < w_lim) ? W[woff] : 0.f;
            }
        }

        // Compute 16 kk from smem
#pragma unroll
        for (int kk = 0; kk < BK2; kk++) {
            const float* arow = As + kk * AS_ROW + ty * 8;
            float4 af0 = *(const float4*)arow;
            float4 af1 = *(const float4*)(arow + 4);
            u64t a2[8];
            a2[0] = dup2(af0.x); a2[1] = dup2(af0.y);
            a2[2] = dup2(af0.z); a2[3] = dup2(af0.w);
            a2[4] = dup2(af1.x); a2[5] = dup2(af1.y);
            a2[6] = dup2(af1.z); a2[7] = dup2(af1.w);
            const float* brow = Ws + kk * WS_ROW + tx * WS_GRP;
            ulonglong2 b01 = *(const ulonglong2*)brow;
            ulonglong2 b23 = *(const ulonglong2*)(brow + 4);
            ulonglong2 b45 = *(const ulonglong2*)(brow + 8);
            ulonglong2 b67 = *(const ulonglong2*)(brow + 12);
            u64t b2[8] = {b01.x, b01.y, b23.x, b23.y,
                          b45.x, b45.y, b67.x, b67.y};
#pragma unroll
            for (int i = 0; i < 8; i++)
#pragma unroll
                for (int j = 0; j < 8; j++)
                    fma2(acc2[i][j], a2[i], b2[j]);
        }
        __syncthreads();   // all reads of this chunk done

        if (c + 1 < nchunks) {
#pragma unroll
            for (int it = 0; it < 8; it++) {
                int idx = it * 256 + tid;
                int row = idx >> 4, kc = idx & 15;
                As[kc * AS_ROW + row] = pa[it];
            }
#pragma unroll
            for (int it = 0; it < 16; it++) {
                int idx = it * 256 + tid;
                int n = idx >> 4, kc = idx & 15;
                Ws[kc * WS_ROW + (n >> 4) * WS_GRP + (n & 15)] = pw[it];
            }
            __syncthreads();  // next chunk visible
        }
    }

    // Epilogue: scalar stores, guarded
#pragma unroll
    for (int i = 0; i < 8; i++) {
        size_t rowoff = (size_t)(bm + ty * 8 + i) * N + bn + tx * 16;
#pragma unroll
        for (int j = 0; j < 8; j++) {
            float2 v = unpack2(acc2[i][j]);
            size_t off = rowoff + 2 * j;
            if (c_sel >= 0 || (long long)off < c_lim) C[off] = v.x;
            if (c_sel >= 0 || (long long)(off + 1) < c_lim) C[off + 1] = v.y;
        }
    }
}

// ---------------------------------------------------------------------------
// RoPE (unchanged)
// ---------------------------------------------------------------------------
__global__ void rope_kernel(int sel,
                            const float* __restrict__ cosv, long long cos_lim,
                            const float* __restrict__ sinv, long long sin_lim,
                            int nheads) {
    float* t = f32_buf(sel);
    int idx = blockIdx.x * blockDim.x + threadIdx.x;
    int d = idx & 63;
    int head = (idx >> 6) % nheads;
    int row = idx / (nheads * 64);
    if (row >= M_ROWS) return;
    int tpos = row & (T_SEQ - 1);
    long long coff = (long long)tpos * 64 + d;
    float c = (coff < cos_lim) ? cosv[coff] : 0.f;
    float s = (coff < sin_lim) ? sinv[coff] : 0.f;
    size_t base = (size_t)row * (nheads * HD) + head * HD + 2 * d;
    float re = t[base];
    float im = t[base + 1];
    t[base]     = re * c - im * s;
    t[base + 1] = re * s + im * c;
}

// ---------------------------------------------------------------------------
// Flash attention (round-10 verbatim — isolation of the GEMM variable)
// ---------------------------------------------------------------------------
#define QROW 132
#define PROW 68

__global__ __launch_bounds__(256) void flash_kernel() {
    const float* __restrict__ Q  = g_q;
    const float* __restrict__ Kg = g_k;
    const float* __restrict__ Vg = g_v;
    float* __restrict__ Ctx = g_ctx;

    extern __shared__ float sm[];
    float* Qs  = sm;
    float* KVs = sm + 64 * QROW;
    float* Ps  = KVs + 64 * QROW;

    const int tid = threadIdx.x;
    const int ty = tid >> 4;
    const int tx = tid & 15;
    const int bh = blockIdx.y;
    const int b = bh >> 5;
    const int h = bh & 31;
    const int kvh = h >> 2;
    const int t0 = blockIdx.x << 6;

    const float* qb = Q  + (size_t)(b * T_SEQ + t0) * D_MODEL + h * HD;
    const float* kb = Kg + (size_t)(b * T_SEQ) * D_KV + kvh * HD;
    const float* vb = Vg + (size_t)(b * T_SEQ) * D_KV + kvh * HD;
    const float scale = 0.08838834764831845f;

    for (int i = tid; i < 64 * 32; i += 256) {
        int r = i >> 5;
        int c = (i & 31) << 2;
        float4 v = *(const float4*)(qb + (size_t)r * D_MODEL + c);
        float* dst = Qs + r * QROW + c;
        dst[0] = v.x * scale; dst[1] = v.y * scale;
        dst[2] = v.z * scale; dst[3] = v.w * scale;
    }

    float m_i[4], l_i[4];
    u64t o2[4][4];
#pragma unroll
    for (int i = 0; i < 4; i++) {
        m_i[i] = -1e30f;
        l_i[i] = 0.f;
#pragma unroll
        for (int j = 0; j < 4; j++) o2[i][j] = 0ull;
    }

    for (int s0 = 0; s0 < T_SEQ; s0 += 64) {
        for (int i = tid; i < 64 * 32; i += 256) {
            int r = i >> 5;
            int c = (i & 31) << 2;
            float4 v = *(const float4*)(kb + (size_t)(s0 + r) * D_KV + c);
            float* dst = KVs + r * QROW + c;
            dst[0] = v.x; dst[1] = v.y; dst[2] = v.z; dst[3] = v.w;
        }
        __syncthreads();

        u64t sacc2[4][4];
#pragma unroll
        for (int i = 0; i < 4; i++)
#pragma unroll
            for (int j = 0; j < 4; j++) sacc2[i][j] = 0ull;

        for (int kk = 0; kk < 128; kk += 4) {
            ulonglong2 a2[4], b2[4];
#pragma unroll
            for (int i = 0; i < 4; i++)
                a2[i] = *(const ulonglong2*)&Qs[(ty * 4 + i) * QROW + kk];
#pragma unroll
            for (int j = 0; j < 4; j++)
                b2[j] = *(const ulonglong2*)&KVs[(tx * 4 + j) * QROW + kk];
#pragma unroll
            for (int i = 0; i < 4; i++)
#pragma unroll
                for (int j = 0; j < 4; j++) {
                    fma2(sacc2[i][j], a2[i].x, b2[j].x);
                    fma2(sacc2[i][j], a2[i].y, b2[j].y);
                }
        }

#pragma unroll
        for (int i = 0; i < 4; i++) {
            float sc[4];
#pragma unroll
            for (int j = 0; j < 4; j++) {
                float2 p = unpack2(sacc2[i][j]);
                sc[j] = p.x + p.y;
            }
            float mx = fmaxf(fmaxf(sc[0], sc[1]), fmaxf(sc[2], sc[3]));
#pragma unroll
            for (int off = 1; off < 16; off <<= 1)
                mx = fmaxf(mx, __shfl_xor_sync(0xffffffffu, mx, off));
            float mnew = fmaxf(m_i[i], mx);
            float corr = __expf(m_i[i] - mnew);
            m_i[i] = mnew;
            float p0 = __expf(sc[0] - mnew);
            float p1 = __expf(sc[1] - mnew);
            float p2 = __expf(sc[2] - mnew);
            float p3 = __expf(sc[3] - mnew);
            float rsum = p0 + p1 + p2 + p3;
#pragma unroll
            for (int off = 1; off < 16; off <<= 1)
                rsum += __shfl_xor_sync(0xffffffffu, rsum, off);
            l_i[i] = l_i[i] * corr + rsum;
            u64t c2 = dup2(corr);
#pragma unroll
            for (int j = 0; j < 4; j++) o2[i][j] = mul2(o2[i][j], c2);
            float* pr = Ps + (ty * 4 + i) * PROW + tx * 4;
            pr[0] = p0; pr[1] = p1; pr[2] = p2; pr[3] = p3;
        }
        __syncthreads();

        for (int i = tid; i < 64 * 32; i += 256) {
            int r = i >> 5;
            int c = (i & 31) << 2;
            float4 v = *(const float4*)(vb + (size_t)(s0 + r) * D_KV + c);
            float* dst = KVs + r * QROW + c;
            dst[0] = v.x; dst[1] = v.y; dst[2] = v.z; dst[3] = v.w;
        }
        __syncthreads();

        for (int ss = 0; ss < 64; ss++) {
            ulonglong2 v01 = *(const ulonglong2*)&KVs[ss * QROW + tx * 8];
            ulonglong2 v23 = *(const ulonglong2*)&KVs[ss * QROW + tx * 8 + 4];
#pragma unroll
            for (int i = 0; i < 4; i++) {
                u64t p2v = dup2(Ps[(ty * 4 + i) * PROW + ss]);
                fma2(o2[i][0], p2v, v01.x);
                fma2(o2[i][1], p2v, v01.y);
                fma2(o2[i][2], p2v, v23.x);
                fma2(o2[i][3], p2v, v23.y);
            }
        }
        __syncthreads();
    }

#pragma unroll
    for (int i = 0; i < 4; i++) {
        float inv = 1.f / l_i[i];
        size_t row = (size_t)(b * T_SEQ + t0 + ty * 4 + i);
        float* dst = Ctx + row * D_MODEL + h * HD + tx * 8;
#pragma unroll
        for (int j = 0; j < 4; j++) {
            float2 v = unpack2(o2[i][j]);
            dst[2 * j] = v.x * inv;
            dst[2 * j + 1] = v.y * inv;
        }
    }
}

// ---------------------------------------------------------------------------
// Launch
// ---------------------------------------------------------------------------
extern "C" void kernel_launch(void* const* d_in, const int* in_sizes, int n_in,
                              void* d_out, int out_size) {
    const float* x    = (const float*)d_in[0];
    const float* wq   = (const float*)d_in[1];
    const float* wk   = (const float*)d_in[2];
    const float* wv   = (const float*)d_in[3];
    const float* wo   = (const float*)d_in[4];
    const float* cosv = (const float*)d_in[7];
    const float* sinv = (const float*)d_in[8];
    float* out = (float*)d_out;

    long long xl  = in_sizes[0];
    long long wql = in_sizes[1];
    long long wkl = in_sizes[2];
    long long wvl = in_sizes[3];
    long long wol = in_sizes[4];
    long long cl  = in_sizes[7];
    long long sl  = in_sizes[8];
    long long ol  = out_size;

    const int FLASH_SMEM = (64 * QROW * 2 + 64 * PROW) * 4;  // 84992 bytes
    cudaFuncSetAttribute(flash_kernel,
                         cudaFuncAttributeMaxDynamicSharedMemorySize, FLASH_SMEM);

    // Projections: q = x wq^T, k = x wk^T, v = x wv^T  (N-tile = 256)
    gemm_nt_kernel<<<dim3(16, 64), 256>>>(x, -1, xl, wq, wql,
                                          nullptr, 0, 0, M_ROWS, D_MODEL, D_MODEL);
    gemm_nt_kernel<<<dim3(4, 64), 256>>>(x, -1, xl, wk, wkl,
                                         nullptr, 1, 0, M_ROWS, D_KV, D_MODEL);
    gemm_nt_kernel<<<dim3(4, 64), 256>>>(x, -1, xl, wv, wvl,
                                         nullptr, 2, 0, M_ROWS, D_KV, D_MODEL);

    // RoPE on q (32 heads) and k (8 heads)
    rope_kernel<<<(M_ROWS * NH * 64) / 256, 256>>>(0, cosv, cl, sinv, sl, NH);
    rope_kernel<<<(M_ROWS * NKV * 64) / 256, 256>>>(1, cosv, cl, sinv, sl, NKV);

    // Attention
    flash_kernel<<<dim3(T_SEQ / 64, B_SZ * NH), 256, FLASH_SMEM>>>();

    // Output projection: out = ctx wo^T
    gemm_nt_kernel<<<dim3(16, 64), 256>>>(nullptr, 3, 0, wo, wol,
                                          out, -1, ol, M_ROWS, D_MODEL, D_MODEL);
}

// round 15
// speedup vs baseline: 1.2154x; 1.0006x over previous
#include <cuda_runtime.h>
#include <math.h>
#include <stdint.h>

// Problem constants
#define B_SZ    2
#define T_SEQ   2048
#define M_ROWS  8192
#define D_MODEL 4096
#define D_KV    1024
#define HD      128
#define NH      32
#define NKV     8

// ---------------------------------------------------------------------------
// Scratch: proven-safe footprint — 320 MB, fp32 only (r2/r10/r11 layout).
// ---------------------------------------------------------------------------
__device__ __align__(256) float g_q[(size_t)M_ROWS * D_MODEL];
__device__ __align__(256) float g_k[(size_t)M_ROWS * D_KV];
__device__ __align__(256) float g_v[(size_t)M_ROWS * D_KV];
__device__ __align__(256) float g_ctx[(size_t)M_ROWS * D_MODEL];

__device__ __forceinline__ float* f32_buf(int sel) {
    switch (sel) {
        case 0:  return g_q;
        case 1:  return g_k;
        case 2:  return g_v;
        default: return g_ctx;
    }
}

// ---------------------------------------------------------------------------
// Packed f32x2 helpers
// ---------------------------------------------------------------------------
typedef unsigned long long u64t;

__device__ __forceinline__ void fma2(u64t& d, u64t a, u64t b) {
    asm("fma.rn.f32x2 %0, %1, %2, %0;" : "+l"(d) : "l"(a), "l"(b));
}
__device__ __forceinline__ u64t mul2(u64t a, u64t b) {
    u64t d;
    asm("mul.rn.f32x2 %0, %1, %2;" : "=l"(d) : "l"(a), "l"(b));
    return d;
}
__device__ __forceinline__ u64t dup2(float x) {
    u64t d;
    asm("mov.b64 %0, {%1, %1};" : "=l"(d) : "f"(x));
    return d;
}
__device__ __forceinline__ float2 unpack2(u64t v) {
    float2 f;
    asm("mov.b64 {%0, %1}, %2;" : "=f"(f.x), "=f"(f.y) : "l"(v));
    return f;
}

// ---------------------------------------------------------------------------
// NT GEMM (r11 structure verbatim): C[m,n] = sum_k A[m,k]*W[n,k].
// CTA 128(m) x 256(n), 256 threads, thread tile 8x16, K-chunk 16,
// single-buffer static smem + register prefetch, GUARDED scalar loads on
// harness memory (empirical law: guards are load-bearing on this harness).
// NEW: optional fused RoPE in the epilogue (rotate each (2j,2j+1) pair).
// ---------------------------------------------------------------------------
#define BK2      16
#define AS_ROW   132
#define WS_GRP   36
#define WS_ROW   (16 * WS_GRP)          // 576
#define AS_ELEMS (BK2 * AS_ROW)         // 2112
#define WS_ELEMS (BK2 * WS_ROW)         // 9216

__global__ __launch_bounds__(256, 1) void gemm_nt_kernel(
    const float* __restrict__ Aparam, int a_sel, long long a_lim,
    const float* __restrict__ W, long long w_lim,
    float* __restrict__ Cparam, int c_sel, long long c_lim,
    int M, int N, int K,
    const float* __restrict__ cosv, const float* __restrict__ sinv,
    long long cs_lim, int do_rope) {
    const float* A = (a_sel < 0) ? Aparam : f32_buf(a_sel);
    float* C = (c_sel < 0) ? Cparam : f32_buf(c_sel);

    __shared__ __align__(16) float As[AS_ELEMS];   // 8448 B
    __shared__ __align__(16) float Ws[WS_ELEMS];   // 36864 B

    const int tid = threadIdx.x;
    const int ty = tid >> 4;        // 0..15 -> rows ty*8..+7
    const int tx = tid & 15;        // 0..15 -> cols tx*16..+15
    const int bm = blockIdx.y << 7;
    const int bn = blockIdx.x << 8;

    u64t acc2[8][8];
#pragma unroll
    for (int i = 0; i < 8; i++)
#pragma unroll
        for (int j = 0; j < 8; j++) acc2[i][j] = 0ull;

    float pa[8], pw[16];
    const int lrow = tid >> 1;      // A-load row 0..127
    const int lkb = (tid & 1) << 3; // A-load k offset 0 or 8

    // Load chunk 0 (scalar, guarded)
#pragma unroll
    for (int j = 0; j < 8; j++) {
        size_t aoff = (size_t)(bm + lrow) * K + lkb + j;
        pa[j] = (a_sel >= 0 || (long long)aoff < a_lim) ? A[aoff] : 0.f;
    }
#pragma unroll
    for (int it = 0; it < 16; it++) {
        int idx = it * 256 + tid;
        int n = idx >> 4, kc = idx & 15;
        size_t woff = (size_t)(bn + n) * K + kc;
        pw[it] = ((long long)woff < w_lim) ? W[woff] : 0.f;
    }
    // Store chunk 0
#pragma unroll
    for (int j = 0; j < 8; j++)
        As[(lkb + j) * AS_ROW + lrow] = pa[j];
#pragma unroll
    for (int it = 0; it < 16; it++) {
        int idx = it * 256 + tid;
        int n = idx >> 4, kc = idx & 15;
        Ws[kc * WS_ROW + (n >> 4) * WS_GRP + (n & 15)] = pw[it];
    }
    __syncthreads();

    const int nchunks = K / BK2;
    for (int c = 0; c < nchunks; c++) {
        // Prefetch next chunk into registers (guarded scalar)
        if (c + 1 < nchunks) {
            const int k0 = (c + 1) * BK2;
#pragma unroll
            for (int j = 0; j < 8; j++) {
                size_t aoff = (size_t)(bm + lrow) * K + k0 + lkb + j;
                pa[j] = (a_sel >= 0 || (long long)aoff < a_lim) ? A[aoff] : 0.f;
            }
#pragma unroll
            for (int it = 0; it < 16; it++) {
                int idx = it * 256 + tid;
                int n = idx >> 4, kc = idx & 15;
                size_t woff = (size_t)(bn + n) * K + k0 + kc;
                pw[it] = ((long long)woff < w_lim) ? W[woff] : 0.f;
            }
        }

        // Compute 16 kk from smem
#pragma unroll
        for (int kk = 0; kk < BK2; kk++) {
            const float* arow = As + kk * AS_ROW + ty * 8;
            float4 af0 = *(const float4*)arow;
            float4 af1 = *(const float4*)(arow + 4);
            u64t a2[8];
            a2[0] = dup2(af0.x); a2[1] = dup2(af0.y);
            a2[2] = dup2(af0.z); a2[3] = dup2(af0.w);
            a2[4] = dup2(af1.x); a2[5] = dup2(af1.y);
            a2[6] = dup2(af1.z); a2[7] = dup2(af1.w);
            const float* brow = Ws + kk * WS_ROW + tx * WS_GRP;
            ulonglong2 b01 = *(const ulonglong2*)brow;
            ulonglong2 b23 = *(const ulonglong2*)(brow + 4);
            ulonglong2 b45 = *(const ulonglong2*)(brow + 8);
            ulonglong2 b67 = *(const ulonglong2*)(brow + 12);
            u64t b2[8] = {b01.x, b01.y, b23.x, b23.y,
                          b45.x, b45.y, b67.x, b67.y};
#pragma unroll
            for (int i = 0; i < 8; i++)
#pragma unroll
                for (int j = 0; j < 8; j++)
                    fma2(acc2[i][j], a2[i], b2[j]);
        }
        __syncthreads();

        if (c + 1 < nchunks) {
#pragma unroll
            for (int j = 0; j < 8; j++)
                As[(lkb + j) * AS_ROW + lrow] = pa[j];
#pragma unroll
            for (int it = 0; it < 16; it++) {
                int idx = it * 256 + tid;
                int n = idx >> 4, kc = idx & 15;
                Ws[kc * WS_ROW + (n >> 4) * WS_GRP + (n & 15)] = pw[it];
            }
            __syncthreads();
        }
    }

    // Epilogue: optional fused RoPE, then scalar guarded stores
#pragma unroll
    for (int i = 0; i < 8; i++) {
        int grow = bm + ty * 8 + i;
        int tpos = grow & (T_SEQ - 1);
        size_t rowoff = (size_t)grow * N + bn + tx * 16;
#pragma unroll
        for (int j = 0; j < 8; j++) {
            float2 v = unpack2(acc2[i][j]);
            if (do_rope) {
                int col = bn + tx * 16 + 2 * j;
                int d = (col & 127) >> 1;
                long long co = (long long)tpos * 64 + d;
                float cc = (co < cs_lim) ? cosv[co] : 0.f;
                float ss = (co < cs_lim) ? sinv[co] : 0.f;
                float re = v.x, im = v.y;
                v.x = re * cc - im * ss;
                v.y = re * ss + im * cc;
            }
            size_t off = rowoff + 2 * j;
            if (c_sel >= 0 || (long long)off < c_lim) C[off] = v.x;
            if (c_sel >= 0 || (long long)(off + 1) < c_lim) C[off + 1] = v.y;
        }
    }
}

// ---------------------------------------------------------------------------
// Flash attention (r11 verbatim)
// ---------------------------------------------------------------------------
#define QROW 132
#define PROW 68

__global__ __launch_bounds__(256) void flash_kernel() {
    const float* __restrict__ Q  = g_q;
    const float* __restrict__ Kg = g_k;
    const float* __restrict__ Vg = g_v;
    float* __restrict__ Ctx = g_ctx;

    extern __shared__ float sm[];
    float* Qs  = sm;
    float* KVs = sm + 64 * QROW;
    float* Ps  = KVs + 64 * QROW;

    const int tid = threadIdx.x;
    const int ty = tid >> 4;
    const int tx = tid & 15;
    const int bh = blockIdx.y;
    const int b = bh >> 5;
    const int h = bh & 31;
    const int kvh = h >> 2;
    const int t0 = blockIdx.x << 6;

    const float* qb = Q  + (size_t)(b * T_SEQ + t0) * D_MODEL + h * HD;
    const float* kb = Kg + (size_t)(b * T_SEQ) * D_KV + kvh * HD;
    const float* vb = Vg + (size_t)(b * T_SEQ) * D_KV + kvh * HD;
    const float scale = 0.08838834764831845f;

    for (int i = tid; i < 64 * 32; i += 256) {
        int r = i >> 5;
        int c = (i & 31) << 2;
        float4 v = *(const float4*)(qb + (size_t)r * D_MODEL + c);
        float* dst = Qs + r * QROW + c;
        dst[0] = v.x * scale; dst[1] = v.y * scale;
        dst[2] = v.z * scale; dst[3] = v.w * scale;
    }

    float m_i[4], l_i[4];
    u64t o2[4][4];
#pragma unroll
    for (int i = 0; i < 4; i++) {
        m_i[i] = -1e30f;
        l_i[i] = 0.f;
#pragma unroll
        for (int j = 0; j < 4; j++) o2[i][j] = 0ull;
    }

    for (int s0 = 0; s0 < T_SEQ; s0 += 64) {
        for (int i = tid; i < 64 * 32; i += 256) {
            int r = i >> 5;
            int c = (i & 31) << 2;
            float4 v = *(const float4*)(kb + (size_t)(s0 + r) * D_KV + c);
            float* dst = KVs + r * QROW + c;
            dst[0] = v.x; dst[1] = v.y; dst[2] = v.z; dst[3] = v.w;
        }
        __syncthreads();

        u64t sacc2[4][4];
#pragma unroll
        for (int i = 0; i < 4; i++)
#pragma unroll
            for (int j = 0; j < 4; j++) sacc2[i][j] = 0ull;

        for (int kk = 0; kk < 128; kk += 4) {
            ulonglong2 a2[4], b2[4];
#pragma unroll
            for (int i = 0; i < 4; i++)
                a2[i] = *(const ulonglong2*)&Qs[(ty * 4 + i) * QROW + kk];
#pragma unroll
            for (int j = 0; j < 4; j++)
                b2[j] = *(const ulonglong2*)&KVs[(tx * 4 + j) * QROW + kk];
#pragma unroll
            for (int i = 0; i < 4; i++)
#pragma unroll
                for (int j = 0; j < 4; j++) {
                    fma2(sacc2[i][j], a2[i].x, b2[j].x);
                    fma2(sacc2[i][j], a2[i].y, b2[j].y);
                }
        }

#pragma unroll
        for (int i = 0; i < 4; i++) {
            float sc[4];
#pragma unroll
            for (int j = 0; j < 4; j++) {
                float2 p = unpack2(sacc2[i][j]);
                sc[j] = p.x + p.y;
            }
            float mx = fmaxf(fmaxf(sc[0], sc[1]), fmaxf(sc[2], sc[3]));
#pragma unroll
            for (int off = 1; off < 16; off <<= 1)
                mx = fmaxf(mx, __shfl_xor_sync(0xffffffffu, mx, off));
            float mnew = fmaxf(m_i[i], mx);
            float corr = __expf(m_i[i] - mnew);
            m_i[i] = mnew;
            float p0 = __expf(sc[0] - mnew);
            float p1 = __expf(sc[1] - mnew);
            float p2 = __expf(sc[2] - mnew);
            float p3 = __expf(sc[3] - mnew);
            float rsum = p0 + p1 + p2 + p3;
#pragma unroll
            for (int off = 1; off < 16; off <<= 1)
                rsum += __shfl_xor_sync(0xffffffffu, rsum, off);
            l_i[i] = l_i[i] * corr + rsum;
            u64t c2 = dup2(corr);
#pragma unroll
            for (int j = 0; j < 4; j++) o2[i][j] = mul2(o2[i][j], c2);
            float* pr = Ps + (ty * 4 + i) * PROW + tx * 4;
            pr[0] = p0; pr[1] = p1; pr[2] = p2; pr[3] = p3;
        }
        __syncthreads();

        for (int i = tid; i < 64 * 32; i += 256) {
            int r = i >> 5;
            int c = (i & 31) << 2;
            float4 v = *(const float4*)(vb + (size_t)(s0 + r) * D_KV + c);
            float* dst = KVs + r * QROW + c;
            dst[0] = v.x; dst[1] = v.y; dst[2] = v.z; dst[3] = v.w;
        }
        __syncthreads();

        for (int ss = 0; ss < 64; ss++) {
            ulonglong2 v01 = *(const ulonglong2*)&KVs[ss * QROW + tx * 8];
            ulonglong2 v23 = *(const ulonglong2*)&KVs[ss * QROW + tx * 8 + 4];
#pragma unroll
            for (int i = 0; i < 4; i++) {
                u64t p2v = dup2(Ps[(ty * 4 + i) * PROW + ss]);
                fma2(o2[i][0], p2v, v01.x);
                fma2(o2[i][1], p2v, v01.y);
                fma2(o2[i][2], p2v, v23.x);
                fma2(o2[i][3], p2v, v23.y);
            }
        }
        __syncthreads();
    }

#pragma unroll
    for (int i = 0; i < 4; i++) {
        float inv = 1.f / l_i[i];
        size_t row = (size_t)(b * T_SEQ + t0 + ty * 4 + i);
        float* dst = Ctx + row * D_MODEL + h * HD + tx * 8;
#pragma unroll
        for (int j = 0; j < 4; j++) {
            float2 v = unpack2(o2[i][j]);
            dst[2 * j] = v.x * inv;
            dst[2 * j + 1] = v.y * inv;
        }
    }
}

// ---------------------------------------------------------------------------
// Launch
// ---------------------------------------------------------------------------
extern "C" void kernel_launch(void* const* d_in, const int* in_sizes, int n_in,
                              void* d_out, int out_size) {
    const float* x    = (const float*)d_in[0];
    const float* wq   = (const float*)d_in[1];
    const float* wk   = (const float*)d_in[2];
    const float* wv   = (const float*)d_in[3];
    const float* wo   = (const float*)d_in[4];
    const float* cosv = (const float*)d_in[7];
    const float* sinv = (const float*)d_in[8];
    float* out = (float*)d_out;

    long long xl  = in_sizes[0];
    long long wql = in_sizes[1];
    long long wkl = in_sizes[2];
    long long wvl = in_sizes[3];
    long long wol = in_sizes[4];
    long long cl  = in_sizes[7];
    long long sl  = in_sizes[8];
    long long csl = (cl < sl) ? cl : sl;
    long long ol  = out_size;

    const int FLASH_SMEM = (64 * QROW * 2 + 64 * PROW) * 4;  // 84992 bytes
    cudaFuncSetAttribute(flash_kernel,
                         cudaFuncAttributeMaxDynamicSharedMemorySize, FLASH_SMEM);

    // q = x wq^T (+rope), k = x wk^T (+rope), v = x wv^T
    gemm_nt_kernel<<<dim3(16, 64), 256>>>(x, -1, xl, wq, wql,
                                          nullptr, 0, 0, M_ROWS, D_MODEL, D_MODEL,
                                          cosv, sinv, csl, 1);
    gemm_nt_kernel<<<dim3(4, 64), 256>>>(x, -1, xl, wk, wkl,
                                         nullptr, 1, 0, M_ROWS, D_KV, D_MODEL,
                                         cosv, sinv, csl, 1);
    gemm_nt_kernel<<<dim3(4, 64), 256>>>(x, -1, xl, wv, wvl,
                                         nullptr, 2, 0, M_ROWS, D_KV, D_MODEL,
                                         nullptr, nullptr, 0, 0);

    // Attention
    flash_kernel<<<dim3(T_SEQ / 64, B_SZ * NH), 256, FLASH_SMEM>>>();

    // out = ctx wo^T
    gemm_nt_kernel<<<dim3(16, 64), 256>>>(nullptr, 3, 0, wo, wol,
                                          out, -1, ol, M_ROWS, D_MODEL, D_MODEL,
                                          nullptr, nullptr, 0, 0);
}